// round 16
// baseline (speedup 1.0000x reference)
#include <cuda_runtime.h>
#include <math_constants.h>

constexpr int B = 8;
constexpr int N = 4096;              // == M

// z-strip sort grid
constexpr int   S    = 200;
constexpr float ZLO  = -5.0f;
constexpr float INVW = 20.0f;

constexpr int SPLIT  = 32;           // target chunks
constexpr int CSZ    = N / SPLIT;    // 128 targets per chunk
constexpr int GROUPS = 32;           // query groups per (pass,b)
constexpr int GSZ    = N / GROUPS;   // 128 queries per group
constexpr int NSUB   = 4 * GROUPS;   // 128 subgroups of 32 queries
constexpr int SEEDW  = 512;          // seed window (targets) per group

constexpr int THREADS = 128;         // main block (4 warps)
constexpr int R       = 4;
constexpr int TN      = THREADS * R; // 512 queries per tile
constexpr int NTILES  = N / TN;      // 8

constexpr int SORTB  = 8;            // sort blocks per (c,b)
constexpr int SLICE  = N / SORTB;    // 512 points per sort block

constexpr int TOTALB      = SPLIT * NTILES * 2 * B;  // 4096 main CTAs
constexpr int REDUCERS    = 128;
constexpr int PTS_PER_RED = (B * N) / REDUCERS;      // 256
constexpr int NHIST       = 2 * B * S;               // 3200

// Scratch (no device allocations; zero-initialized at load)
__device__ float4   g_pts[2][B][N];        // (-2x,-2y,-2z, x2+y2+z2), z-sorted
__device__ float2   g_cz[2][B][SPLIT];     // chunk (zmin, zmax)
__device__ unsigned g_best[2][B][N];       // best d2 as uint bits (>=0 floats)
__device__ float    g_ub2[2][B][NSUB];     // per-32-query-subgroup UB^2
__device__ unsigned g_hist[2][B][S];       // strip histogram
__device__ unsigned g_cur[2][B][S];        // scatter cursors
__device__ float    g_acc[4];              // rowsum, sqrtsum, colsum, uncsum
__device__ unsigned g_count  = 0;          // main-CTA ticket
__device__ unsigned g_count2 = 0;          // reducer ticket

// ---------------------------------------------------------------------------
// hist: grid (2, B, SORTB) x 256. Global-atomic strip histogram.
// ---------------------------------------------------------------------------
__global__ void __launch_bounds__(256)
hist_kernel(const float* __restrict__ pred, const float* __restrict__ targ)
{
    const int c = blockIdx.x, b = blockIdx.y, blk = blockIdx.z;
    const int tid = threadIdx.x;
    const float* src = (c == 0 ? pred : targ) + (size_t)b * N * 3;

    if (c == 0 && b == 0 && blk == 0 && tid < 4) g_acc[tid] = 0.f;

    const int i0 = blk * SLICE;
    for (int i = i0 + tid; i < i0 + SLICE; i += 256) {
        const float z = src[i * 3 + 2];
        const int s = min(max((int)((z - ZLO) * INVW), 0), S - 1);
        atomicAdd(&g_hist[c][b][s], 1u);
    }
}

// ---------------------------------------------------------------------------
// scatter: grid (2, B, SORTB) x 256. Local re-scan of the (c,b) histogram,
// then global-cursor scatter. Within-strip order nondeterministic (harmless).
// ---------------------------------------------------------------------------
__global__ void __launch_bounds__(256)
scatter_kernel(const float* __restrict__ pred, const float* __restrict__ targ)
{
    __shared__ int scanA[256], scanB[256], start[256];
    const int c = blockIdx.x, b = blockIdx.y, blk = blockIdx.z;
    const int tid = threadIdx.x;
    const float* src = (c == 0 ? pred : targ) + (size_t)b * N * 3;

    const int v = (tid < S) ? (int)g_hist[c][b][tid] : 0;
    scanA[tid] = v;
    __syncthreads();
    int* sA = scanA; int* sB = scanB;
#pragma unroll
    for (int off = 1; off < 256; off <<= 1) {
        sB[tid] = sA[tid] + ((tid >= off) ? sA[tid - off] : 0);
        int* t = sA; sA = sB; sB = t;
        __syncthreads();
    }
    start[tid] = sA[tid] - v;
    __syncthreads();

    const int i0 = blk * SLICE;
    for (int i = i0 + tid; i < i0 + SLICE; i += 256) {
        const float x = src[i * 3 + 0], y = src[i * 3 + 1], z = src[i * 3 + 2];
        const int s = min(max((int)((z - ZLO) * INVW), 0), S - 1);
        const int pos = start[s] + (int)atomicAdd(&g_cur[c][b][s], 1u);
        g_pts[c][b][pos] = make_float4(-2.f * x, -2.f * y, -2.f * z,
                                       x * x + y * y + z * z);
    }
}

// ---------------------------------------------------------------------------
// seed: per 128-query group, dense scan of 512 index-adjacent (z-near)
// targets -> per-query upper bound into g_best; per-32-subgroup UB^2 (tight);
// chunk z-bounds for chunk g of cloud tc; unc partial sum (pass 0 only).
// ---------------------------------------------------------------------------
__global__ void __launch_bounds__(GSZ)
seed_kernel(const float* __restrict__ unc)
{
    __shared__ float4 st[SEEDW];         // 8KB
    __shared__ float  szmn[GSZ / 32], szmx[GSZ / 32];

    const int g = blockIdx.x, b = blockIdx.y, pass = blockIdx.z;
    const int tid = threadIdx.x, lane = tid & 31, w = tid >> 5;
    const int qc = pass, tc = 1 - pass;
    const int i0 = g * GSZ;
    const int wlo = min(max(i0 - 192, 0), N - SEEDW);

#pragma unroll
    for (int s = 0; s < SEEDW / GSZ; s++)
        st[tid + s * GSZ] = g_pts[tc][b][wlo + tid + s * GSZ];

    const float4 Q  = g_pts[qc][b][i0 + tid];
    const float qx  = -0.5f * Q.x, qy = -0.5f * Q.y, qz = -0.5f * Q.z;
    const float qn2 = Q.w;

    // chunk z-bounds for chunk g of cloud tc (CSZ == GSZ == 128)
    {
        float z = -0.5f * g_pts[tc][b][g * CSZ + tid].z;
        float zmn = z, zmx = z;
#pragma unroll
        for (int o = 16; o > 0; o >>= 1) {
            zmn = fminf(zmn, __shfl_xor_sync(0xffffffffu, zmn, o));
            zmx = fmaxf(zmx, __shfl_xor_sync(0xffffffffu, zmx, o));
        }
        if (lane == 0) { szmn[w] = zmn; szmx[w] = zmx; }
    }
    __syncthreads();                     // st staged + szmn ready
    if (tid == 0) {
        const float zmn = fminf(fminf(szmn[0], szmn[1]), fminf(szmn[2], szmn[3]));
        const float zmx = fmaxf(fmaxf(szmx[0], szmx[1]), fmaxf(szmx[2], szmx[3]));
        g_cz[tc][b][g] = make_float2(zmn, zmx);
    }

    float b0 = CUDART_INF_F, b1 = CUDART_INF_F;
#pragma unroll 4
    for (int j = 0; j < SEEDW; j += 2) {
        const float4 t0 = st[j], t1 = st[j + 1];
        float d0 = fmaf(qz, t0.z, t0.w);
        float d1 = fmaf(qz, t1.z, t1.w);
        d0 = fmaf(qy, t0.y, d0);  d1 = fmaf(qy, t1.y, d1);
        d0 = fmaf(qx, t0.x, d0);  d1 = fmaf(qx, t1.x, d1);
        b0 = fminf(b0, d0);       b1 = fminf(b1, d1);
    }
    const float d2 = fmaxf(qn2 + fminf(b0, b1), 0.f);   // >=0 squared dist

    g_best[pass][b][i0 + tid] = __float_as_uint(d2);

    // per-32-subgroup UB^2 (this warp == one subgroup of 32 queries)
    float mx = d2;
#pragma unroll
    for (int o = 16; o > 0; o >>= 1)
        mx = fmaxf(mx, __shfl_down_sync(0xffffffffu, mx, o));
    if (lane == 0) g_ub2[pass][b][g * 4 + w] = mx;

    if (pass == 0) {                     // unc sum (order-free)
        float u = unc[b * N + i0 + tid];
#pragma unroll
        for (int o = 16; o > 0; o >>= 1)
            u += __shfl_down_sync(0xffffffffu, u, o);
        if (lane == 0) atomicAdd(&g_acc[3], u);
    }
}

// ---------------------------------------------------------------------------
// main: 32 chunks x 8 tiles x 2B CTAs, 128 thr. Per-(warp,j) skip at
// 32-query granularity (warp-uniform branch: shuffle z-range + uniform UB).
// Survivors run a dense smem loop; merged via atomicMin on float bits.
// Fused ticket reduce + finalize; zz==0 blocks reset sort counters.
// ---------------------------------------------------------------------------
__global__ void __launch_bounds__(THREADS)
main_kernel(float* __restrict__ out)
{
    __shared__ float4   sc[CSZ];
    __shared__ int      s_need;
    __shared__ unsigned s_ticket;
    __shared__ float    red[3][THREADS / 32];

    const int tid  = threadIdx.x, lane = tid & 31, w = tid >> 5;
    const int split = blockIdx.x, ntile = blockIdx.y, zz = blockIdx.z;
    const int b = zz & (B - 1), pass = zz >> 3;
    const int tc = 1 - pass;
    const int qbase = ntile * TN + w * GSZ + lane;

    const float4* __restrict__ T = g_pts[tc][b];

    if (tid == 0) s_need = 0;

    // reset sort scratch for next graph replay
    if (zz == 0) {
        const int flat = (split * NTILES + ntile) * THREADS + tid;
        if (flat < NHIST) {
            (&g_hist[0][0][0])[flat] = 0u;
            (&g_cur[0][0][0])[flat]  = 0u;
        }
    }

    float px[R], py[R], pz[R], pn2[R];
#pragma unroll
    for (int j = 0; j < R; j++) {
        const float4 Q = g_pts[pass][b][qbase + 32 * j];
        px[j] = -0.5f * Q.x; py[j] = -0.5f * Q.y; pz[j] = -0.5f * Q.z;
        pn2[j] = Q.w;
    }

    // per-(warp,j) skip: subgroup z-range vs chunk z-range vs subgroup UB^2
    const float2 cz = g_cz[tc][b][split];
    bool skipj[R];
    int  any = 0;
#pragma unroll
    for (int j = 0; j < R; j++) {
        float mn = pz[j], mx = pz[j];
#pragma unroll
        for (int o = 16; o > 0; o >>= 1) {
            mn = fminf(mn, __shfl_xor_sync(0xffffffffu, mn, o));
            mx = fmaxf(mx, __shfl_xor_sync(0xffffffffu, mx, o));
        }
        const float gap = fmaxf(fmaxf(cz.x - mx, mn - cz.y), 0.f);
        const int sub = ntile * 16 + w * 4 + j;
        skipj[j] = (gap * gap >= g_ub2[pass][b][sub]);
        if (!skipj[j]) any = 1;
    }

    __syncthreads();
    if (lane == 0 && any) atomicAdd(&s_need, 1);
    __syncthreads();

    if (s_need > 0) {                        // some warp scans this chunk
        sc[tid] = T[split * CSZ + tid];      // CSZ == THREADS
        __syncthreads();

#pragma unroll
        for (int j = 0; j < R; j++) {
            if (!skipj[j]) {                 // warp-uniform branch
                float r0 = CUDART_INF_F, r1 = CUDART_INF_F;
#pragma unroll 4
                for (int k = 0; k < CSZ; k += 2) {
                    const float4 t0 = sc[k], t1 = sc[k + 1];
                    float d0 = fmaf(pz[j], t0.z, t0.w);
                    float d1 = fmaf(pz[j], t1.z, t1.w);
                    d0 = fmaf(py[j], t0.y, d0);
                    d1 = fmaf(py[j], t1.y, d1);
                    d0 = fmaf(px[j], t0.x, d0);
                    d1 = fmaf(px[j], t1.x, d1);
                    r0 = fminf(r0, d0);
                    r1 = fminf(r1, d1);
                }
                const float d2 = fmaxf(pn2[j] + fminf(r0, r1), 0.f);
                atomicMin(&g_best[pass][b][qbase + 32 * j],
                          __float_as_uint(d2));
            }
        }
    }

    // ---- ticket: last REDUCERS finishers reduce + finalize ----
    __threadfence();
    __syncthreads();
    if (tid == 0) s_ticket = atomicAdd(&g_count, 1u);
    __syncthreads();
    const unsigned my = s_ticket;
    if (my < (unsigned)(TOTALB - REDUCERS)) return;

    if (tid == 0) {
        while (*((volatile unsigned*)&g_count) < (unsigned)TOTALB)
            __nanosleep(64);
    }
    __syncthreads();
    __threadfence();

    const int rid  = (int)my - (TOTALB - REDUCERS);
    const int base = rid * PTS_PER_RED;

    float s_row = 0.f, s_sqrt = 0.f, s_col = 0.f;
#pragma unroll
    for (int it = 0; it < PTS_PER_RED / THREADS; it++) {
        const int idx = base + it * THREADS + tid;
        const int bb = idx >> 12, nn = idx & (N - 1);

        const float m = __uint_as_float(g_best[0][bb][nn]);
        s_row  += m;
        s_sqrt += sqrtf(m);
        s_col  += __uint_as_float(g_best[1][bb][nn]);
    }
#pragma unroll
    for (int o = 16; o > 0; o >>= 1) {
        s_row  += __shfl_down_sync(0xffffffffu, s_row,  o);
        s_sqrt += __shfl_down_sync(0xffffffffu, s_sqrt, o);
        s_col  += __shfl_down_sync(0xffffffffu, s_col,  o);
    }
    if (lane == 0) {
        red[0][w] = s_row; red[1][w] = s_sqrt; red[2][w] = s_col;
    }
    __syncthreads();
    if (tid == 0) {
        float a0 = 0.f, a1 = 0.f, a2 = 0.f;
#pragma unroll
        for (int ww = 0; ww < THREADS / 32; ww++) {
            a0 += red[0][ww]; a1 += red[1][ww]; a2 += red[2][ww];
        }
        atomicAdd(&g_acc[0], a0);
        atomicAdd(&g_acc[1], a1);
        atomicAdd(&g_acc[2], a2);

        __threadfence();
        const unsigned done = atomicAdd(&g_count2, 1u);
        if (done == (unsigned)(REDUCERS - 1)) {
            const float inv = 1.0f / (float)(B * N);
            const float chamfer = (g_acc[0] + g_acc[2]) * inv;
            const float emd     = g_acc[1] * inv;
            const float u       = g_acc[3] * inv;
            out[0] = chamfer * 1.0f + emd * 0.5f + u * 0.01f;
            g_count  = 0;                   // reset for graph replay
            g_count2 = 0;
        }
    }
}

// ---------------------------------------------------------------------------
extern "C" void kernel_launch(void* const* d_in, const int* in_sizes, int n_in,
                              void* d_out, int out_size)
{
    const float* pred = (const float*)d_in[0];   // [B, N, 3]
    const float* targ = (const float*)d_in[1];   // [B, M, 3]
    const float* unc  = (const float*)d_in[2];   // [B, N]
    float* out = (float*)d_out;

    dim3 hgrid(2, B, SORTB);                     // 128 blocks
    hist_kernel<<<hgrid, 256>>>(pred, targ);
    scatter_kernel<<<hgrid, 256>>>(pred, targ);

    dim3 sgrid(GROUPS, B, 2);                    // 512 blocks x 128
    seed_kernel<<<sgrid, GSZ>>>(unc);

    dim3 mgrid(SPLIT, NTILES, 2 * B);            // 4096 blocks x 128
    main_kernel<<<mgrid, THREADS>>>(out);
}

// round 17
// speedup vs baseline: 1.1079x; 1.1079x over previous
#include <cuda_runtime.h>
#include <math_constants.h>

constexpr int B = 8;
constexpr int N = 4096;              // == M

// z-strip sort grid
constexpr int   S    = 200;
constexpr float ZLO  = -5.0f;
constexpr float INVW = 20.0f;

constexpr int SPLIT  = 32;           // target chunks
constexpr int CSZ    = N / SPLIT;    // 128 targets per chunk
constexpr int GROUPS = 32;           // query groups per (pass,b)
constexpr int GSZ    = N / GROUPS;   // 128 queries per group
constexpr int NSUB   = 4 * GROUPS;   // 128 subgroups of 32 queries
constexpr int SEEDW  = 512;          // seed window (targets) per group

constexpr int THREADS = 128;         // main block (4 warps)
constexpr int R       = 4;
constexpr int TN      = THREADS * R; // 512 queries per tile
constexpr int NTILES  = N / TN;      // 8

constexpr int SORTB  = 8;            // sort blocks per (c,b)
constexpr int SLICE  = N / SORTB;    // 512 points per sort block

constexpr int TOTALB      = SPLIT * NTILES * 2 * B;  // 4096 main CTAs
constexpr int REDUCERS    = 128;
constexpr int PTS_PER_RED = (B * N) / REDUCERS;      // 256
constexpr int NHIST       = 2 * B * S;               // 3200

// Scratch (no device allocations; zero-initialized at load)
__device__ float4   g_pts[2][B][N];        // (-2x,-2y,-2z, x2+y2+z2), z-sorted
__device__ float2   g_cz[2][B][SPLIT];     // chunk (zmin, zmax)
__device__ float4   g_sub[2][B][NSUB];     // subgroup (zmin, zmax, UB^2, -)
__device__ unsigned g_best[2][B][N];       // best d2 as uint bits (>=0 floats)
__device__ unsigned g_hist[2][B][S];       // strip histogram
__device__ unsigned g_cur[2][B][S];        // scatter cursors
__device__ float    g_acc[4];              // rowsum, sqrtsum, colsum, uncsum
__device__ unsigned g_count  = 0;          // main-CTA ticket
__device__ unsigned g_count2 = 0;          // reducer ticket

// ---------------------------------------------------------------------------
// hist: grid (2, B, SORTB) x 256. Global-atomic strip histogram.
// ---------------------------------------------------------------------------
__global__ void __launch_bounds__(256)
hist_kernel(const float* __restrict__ pred, const float* __restrict__ targ)
{
    const int c = blockIdx.x, b = blockIdx.y, blk = blockIdx.z;
    const int tid = threadIdx.x;
    const float* src = (c == 0 ? pred : targ) + (size_t)b * N * 3;

    if (c == 0 && b == 0 && blk == 0 && tid < 4) g_acc[tid] = 0.f;

    const int i0 = blk * SLICE;
    for (int i = i0 + tid; i < i0 + SLICE; i += 256) {
        const float z = src[i * 3 + 2];
        const int s = min(max((int)((z - ZLO) * INVW), 0), S - 1);
        atomicAdd(&g_hist[c][b][s], 1u);
    }
}

// ---------------------------------------------------------------------------
// scatter: grid (2, B, SORTB) x 256. Local re-scan of the (c,b) histogram,
// then global-cursor scatter. Within-strip order nondeterministic (harmless).
// ---------------------------------------------------------------------------
__global__ void __launch_bounds__(256)
scatter_kernel(const float* __restrict__ pred, const float* __restrict__ targ)
{
    __shared__ int scanA[256], scanB[256], start[256];
    const int c = blockIdx.x, b = blockIdx.y, blk = blockIdx.z;
    const int tid = threadIdx.x;
    const float* src = (c == 0 ? pred : targ) + (size_t)b * N * 3;

    const int v = (tid < S) ? (int)g_hist[c][b][tid] : 0;
    scanA[tid] = v;
    __syncthreads();
    int* sA = scanA; int* sB = scanB;
#pragma unroll
    for (int off = 1; off < 256; off <<= 1) {
        sB[tid] = sA[tid] + ((tid >= off) ? sA[tid - off] : 0);
        int* t = sA; sA = sB; sB = t;
        __syncthreads();
    }
    start[tid] = sA[tid] - v;
    __syncthreads();

    const int i0 = blk * SLICE;
    for (int i = i0 + tid; i < i0 + SLICE; i += 256) {
        const float x = src[i * 3 + 0], y = src[i * 3 + 1], z = src[i * 3 + 2];
        const int s = min(max((int)((z - ZLO) * INVW), 0), S - 1);
        const int pos = start[s] + (int)atomicAdd(&g_cur[c][b][s], 1u);
        g_pts[c][b][pos] = make_float4(-2.f * x, -2.f * y, -2.f * z,
                                       x * x + y * y + z * z);
    }
}

// ---------------------------------------------------------------------------
// seed: per 128-query group, dense scan of 512 index-adjacent (z-near)
// targets -> per-query upper bound into g_best; per-32-subgroup
// (zmin, zmax, UB^2) into g_sub; chunk z-bounds; unc sum (pass 0 only).
// ---------------------------------------------------------------------------
__global__ void __launch_bounds__(GSZ)
seed_kernel(const float* __restrict__ unc)
{
    __shared__ float4 st[SEEDW];         // 8KB
    __shared__ float  szmn[GSZ / 32], szmx[GSZ / 32];

    const int g = blockIdx.x, b = blockIdx.y, pass = blockIdx.z;
    const int tid = threadIdx.x, lane = tid & 31, w = tid >> 5;
    const int qc = pass, tc = 1 - pass;
    const int i0 = g * GSZ;
    const int wlo = min(max(i0 - 192, 0), N - SEEDW);

#pragma unroll
    for (int s = 0; s < SEEDW / GSZ; s++)
        st[tid + s * GSZ] = g_pts[tc][b][wlo + tid + s * GSZ];

    const float4 Q  = g_pts[qc][b][i0 + tid];
    const float qx  = -0.5f * Q.x, qy = -0.5f * Q.y, qz = -0.5f * Q.z;
    const float qn2 = Q.w;

    // chunk z-bounds for chunk g of cloud tc (CSZ == GSZ == 128)
    {
        float z = -0.5f * g_pts[tc][b][g * CSZ + tid].z;
        float zmn = z, zmx = z;
#pragma unroll
        for (int o = 16; o > 0; o >>= 1) {
            zmn = fminf(zmn, __shfl_xor_sync(0xffffffffu, zmn, o));
            zmx = fmaxf(zmx, __shfl_xor_sync(0xffffffffu, zmx, o));
        }
        if (lane == 0) { szmn[w] = zmn; szmx[w] = zmx; }
    }
    __syncthreads();                     // st staged + szmn ready
    if (tid == 0) {
        const float zmn = fminf(fminf(szmn[0], szmn[1]), fminf(szmn[2], szmn[3]));
        const float zmx = fmaxf(fmaxf(szmx[0], szmx[1]), fmaxf(szmx[2], szmx[3]));
        g_cz[tc][b][g] = make_float2(zmn, zmx);
    }

    float b0 = CUDART_INF_F, b1 = CUDART_INF_F;
#pragma unroll 4
    for (int j = 0; j < SEEDW; j += 2) {
        const float4 t0 = st[j], t1 = st[j + 1];
        float d0 = fmaf(qz, t0.z, t0.w);
        float d1 = fmaf(qz, t1.z, t1.w);
        d0 = fmaf(qy, t0.y, d0);  d1 = fmaf(qy, t1.y, d1);
        d0 = fmaf(qx, t0.x, d0);  d1 = fmaf(qx, t1.x, d1);
        b0 = fminf(b0, d0);       b1 = fminf(b1, d1);
    }
    const float d2 = fmaxf(qn2 + fminf(b0, b1), 0.f);   // >=0 squared dist

    g_best[pass][b][i0 + tid] = __float_as_uint(d2);

    // per-32-subgroup (zmin, zmax, UB^2) — this warp == one subgroup
    {
        float mx = d2, zn = qz, zx = qz;
#pragma unroll
        for (int o = 16; o > 0; o >>= 1) {
            mx = fmaxf(mx, __shfl_xor_sync(0xffffffffu, mx, o));
            zn = fminf(zn, __shfl_xor_sync(0xffffffffu, zn, o));
            zx = fmaxf(zx, __shfl_xor_sync(0xffffffffu, zx, o));
        }
        if (lane == 0)
            g_sub[pass][b][g * 4 + w] = make_float4(zn, zx, mx, 0.f);
    }

    if (pass == 0) {                     // unc sum (order-free)
        float u = unc[b * N + i0 + tid];
#pragma unroll
        for (int o = 16; o > 0; o >>= 1)
            u += __shfl_down_sync(0xffffffffu, u, o);
        if (lane == 0) atomicAdd(&g_acc[3], u);
    }
}

// ---------------------------------------------------------------------------
// main: 32 chunks x 8 tiles x 2B CTAs, 128 thr. Warp skip = AND of 4
// subgroup tests (precomputed bounds, no shuffles). Surviving warps run the
// amortized dense smem loop over ALL 4 j (extra results are true chunk mins
// -> atomicMin merge keeps exactness). zz==0 blocks reset sort counters.
// Fused ticket reduce + finalize.
// ---------------------------------------------------------------------------
__global__ void __launch_bounds__(THREADS)
main_kernel(float* __restrict__ out)
{
    __shared__ float4   sc[CSZ];
    __shared__ int      s_need;
    __shared__ unsigned s_ticket;
    __shared__ float    red[3][THREADS / 32];

    const int tid  = threadIdx.x, lane = tid & 31, w = tid >> 5;
    const int split = blockIdx.x, ntile = blockIdx.y, zz = blockIdx.z;
    const int b = zz & (B - 1), pass = zz >> 3;
    const int tc = 1 - pass;
    const int qbase = ntile * TN + w * GSZ + lane;

    const float4* __restrict__ T = g_pts[tc][b];

    if (tid == 0) s_need = 0;

    // reset sort scratch for next graph replay
    if (zz == 0) {
        const int flat = (split * NTILES + ntile) * THREADS + tid;
        if (flat < NHIST) {
            (&g_hist[0][0][0])[flat] = 0u;
            (&g_cur[0][0][0])[flat]  = 0u;
        }
    }

    // warp skip test: 4 uniform subgroup-bound loads, no shuffles
    const float2 cz = g_cz[tc][b][split];
    bool need = false;
#pragma unroll
    for (int j = 0; j < R; j++) {
        const float4 sv = g_sub[pass][b][ntile * 16 + w * 4 + j];
        const float gap = fmaxf(fmaxf(cz.x - sv.y, sv.x - cz.y), 0.f);
        if (gap * gap < sv.z) need = true;
    }

    __syncthreads();
    if (lane == 0 && need) atomicAdd(&s_need, 1);
    __syncthreads();

    if (s_need > 0) {                        // some warp scans this chunk
        sc[tid] = T[split * CSZ + tid];      // CSZ == THREADS
        __syncthreads();

        if (need) {                          // warp-uniform branch
            float px[R], py[R], pz[R], pn2[R], r[R];
#pragma unroll
            for (int j = 0; j < R; j++) {
                const float4 Q = g_pts[pass][b][qbase + 32 * j];
                px[j] = -0.5f * Q.x; py[j] = -0.5f * Q.y; pz[j] = -0.5f * Q.z;
                pn2[j] = Q.w;  r[j] = CUDART_INF_F;
            }
#pragma unroll 4
            for (int k = 0; k < CSZ; k++) {  // LDS amortized over 4 j
                const float4 v = sc[k];
#pragma unroll
                for (int j = 0; j < R; j++) {
                    float d = fmaf(pz[j], v.z, v.w);
                    d = fmaf(py[j], v.y, d);
                    d = fmaf(px[j], v.x, d);
                    r[j] = fminf(r[j], d);
                }
            }
            unsigned* o = &g_best[pass][b][0];
#pragma unroll
            for (int j = 0; j < R; j++) {
                const float d2 = fmaxf(pn2[j] + r[j], 0.f);
                atomicMin(&o[qbase + 32 * j], __float_as_uint(d2));
            }
        }
    }

    // ---- ticket: last REDUCERS finishers reduce + finalize ----
    __threadfence();
    __syncthreads();
    if (tid == 0) s_ticket = atomicAdd(&g_count, 1u);
    __syncthreads();
    const unsigned my = s_ticket;
    if (my < (unsigned)(TOTALB - REDUCERS)) return;

    if (tid == 0) {
        while (*((volatile unsigned*)&g_count) < (unsigned)TOTALB)
            __nanosleep(64);
    }
    __syncthreads();
    __threadfence();

    const int rid  = (int)my - (TOTALB - REDUCERS);
    const int base = rid * PTS_PER_RED;

    float s_row = 0.f, s_sqrt = 0.f, s_col = 0.f;
#pragma unroll
    for (int it = 0; it < PTS_PER_RED / THREADS; it++) {
        const int idx = base + it * THREADS + tid;
        const int bb = idx >> 12, nn = idx & (N - 1);

        const float m = __uint_as_float(g_best[0][bb][nn]);
        s_row  += m;
        s_sqrt += sqrtf(m);
        s_col  += __uint_as_float(g_best[1][bb][nn]);
    }
#pragma unroll
    for (int o = 16; o > 0; o >>= 1) {
        s_row  += __shfl_down_sync(0xffffffffu, s_row,  o);
        s_sqrt += __shfl_down_sync(0xffffffffu, s_sqrt, o);
        s_col  += __shfl_down_sync(0xffffffffu, s_col,  o);
    }
    if (lane == 0) {
        red[0][w] = s_row; red[1][w] = s_sqrt; red[2][w] = s_col;
    }
    __syncthreads();
    if (tid == 0) {
        float a0 = 0.f, a1 = 0.f, a2 = 0.f;
#pragma unroll
        for (int ww = 0; ww < THREADS / 32; ww++) {
            a0 += red[0][ww]; a1 += red[1][ww]; a2 += red[2][ww];
        }
        atomicAdd(&g_acc[0], a0);
        atomicAdd(&g_acc[1], a1);
        atomicAdd(&g_acc[2], a2);

        __threadfence();
        const unsigned done = atomicAdd(&g_count2, 1u);
        if (done == (unsigned)(REDUCERS - 1)) {
            const float inv = 1.0f / (float)(B * N);
            const float chamfer = (g_acc[0] + g_acc[2]) * inv;
            const float emd     = g_acc[1] * inv;
            const float u       = g_acc[3] * inv;
            out[0] = chamfer * 1.0f + emd * 0.5f + u * 0.01f;
            g_count  = 0;                   // reset for graph replay
            g_count2 = 0;
        }
    }
}

// ---------------------------------------------------------------------------
extern "C" void kernel_launch(void* const* d_in, const int* in_sizes, int n_in,
                              void* d_out, int out_size)
{
    const float* pred = (const float*)d_in[0];   // [B, N, 3]
    const float* targ = (const float*)d_in[1];   // [B, M, 3]
    const float* unc  = (const float*)d_in[2];   // [B, N]
    float* out = (float*)d_out;

    dim3 hgrid(2, B, SORTB);                     // 128 blocks
    hist_kernel<<<hgrid, 256>>>(pred, targ);
    scatter_kernel<<<hgrid, 256>>>(pred, targ);

    dim3 sgrid(GROUPS, B, 2);                    // 512 blocks x 128
    seed_kernel<<<sgrid, GSZ>>>(unc);

    dim3 mgrid(SPLIT, NTILES, 2 * B);            // 4096 blocks x 128
    main_kernel<<<mgrid, THREADS>>>(out);
}